// round 1
// baseline (speedup 1.0000x reference)
#include <cuda_runtime.h>
#include <math.h>

// ---------------------------------------------------------------------------
// Problem constants
// ---------------------------------------------------------------------------
// B=8, L=1024, D_MODEL=2048, H=8, DK=256, D_INNER=4096, D_STATE=16,
// D_CONV=4, DT_RANK=128.  M rows = B*L = 8192.
// Output: [2, 8, 1024, 2048] fp32  (att_feats then src)

// ---------------------------------------------------------------------------
// Scratch (single __device__ global; allocation-free per harness rules)
// ---------------------------------------------------------------------------
constexpr size_t SZ_MD   = 8192ULL * 2048;   // 16,777,216
constexpr size_t SZ_SC   = 64ULL * 1024 * 1024; // 67,108,864 (scores)
constexpr size_t SZ_XZ   = 8192ULL * 8192;   // 67,108,864
constexpr size_t SZ_MI   = 8192ULL * 4096;   // 33,554,432
constexpr size_t SZ_DBC  = 8192ULL * 160;    // 1,310,720

constexpr size_t OFF_Q   = 0;
constexpr size_t OFF_K   = OFF_Q   + SZ_MD;
constexpr size_t OFF_V   = OFF_K   + SZ_MD;
constexpr size_t OFF_S   = OFF_V   + SZ_MD;
constexpr size_t OFF_ATT = OFF_S   + SZ_SC;
constexpr size_t OFF_XZ  = OFF_ATT + SZ_MD;
constexpr size_t OFF_XS  = OFF_XZ  + SZ_XZ;
constexpr size_t OFF_E   = OFF_XS  + SZ_MI;
constexpr size_t OFF_DBC = OFF_E   + SZ_MI;
constexpr size_t OFF_DT  = OFF_DBC + SZ_DBC;
constexpr size_t OFF_Y   = OFF_DT  + SZ_MI;
constexpr size_t OFF_Y2  = OFF_Y   + SZ_MI;
constexpr size_t SCRATCH_TOTAL = OFF_Y2 + SZ_MI;   // ~370.4M floats (~1.48 GB)

__device__ float g_buf[SCRATCH_TOTAL];

// ---------------------------------------------------------------------------
// Generic tiled SGEMM:  C = A(MxK) * B + bias
//   TRANSB=false : B is row-major [K,N] (ldb)
//   TRANSB=true  : B is row-major [N,K] (ldb)  (i.e. C = A * B^T)
// Batched via blockIdx.z with composite offsets:
//   off = (z/zdiv)*s1 + (z%zdiv)*s2   per operand.
// Requirements used here: K%8==0, N%4==0, all base ptrs / lda / ldb 4-float
// aligned (true for every call in this file). M/N bounds are predicated.
// ---------------------------------------------------------------------------
template <bool TRANSB>
__global__ __launch_bounds__(256, 2)
void sgemm_kernel(const float* __restrict__ Ag, const float* __restrict__ Bg,
                  const float* __restrict__ bias, float* __restrict__ Cg,
                  int M, int N, int K, int lda, int ldb, int ldc,
                  int zdiv,
                  long long sA1, long long sA2,
                  long long sB1, long long sB2,
                  long long sC1, long long sC2)
{
    const int z  = blockIdx.z;
    const int zo = z / zdiv, zi = z % zdiv;
    const float* A = Ag + zo * sA1 + zi * sA2;
    const float* B = Bg + zo * sB1 + zi * sB2;
    float*       C = Cg + zo * sC1 + zi * sC2;

    __shared__ float As[8][128];
    __shared__ float Bs[8][132];

    const int tid = threadIdx.x;
    const int m0 = blockIdx.y * 128;
    const int n0 = blockIdx.x * 128;

    const int arow = tid >> 1;            // 0..127
    const int acol = (tid & 1) * 4;       // 0 or 4
    const int brow = tid >> 5;            // 0..7   (NN)
    const int bcol = (tid & 31) * 4;      // 0..124 (NN)
    // NT reuses arow/acol mapping for B ([N,K] rows)

    const int row_c = (tid >> 4) * 8;
    const int col_c = (tid & 15) * 8;

    float acc[8][8];
#pragma unroll
    for (int i = 0; i < 8; i++)
#pragma unroll
        for (int j = 0; j < 8; j++) acc[i][j] = 0.f;

    for (int k0 = 0; k0 < K; k0 += 8) {
        // ---- load A tile [128 x 8] -> As[k][m]
        {
            const int m = m0 + arow;
            float4 av = make_float4(0.f, 0.f, 0.f, 0.f);
            if (m < M)
                av = *reinterpret_cast<const float4*>(A + (long long)m * lda + k0 + acol);
            As[acol + 0][arow] = av.x;
            As[acol + 1][arow] = av.y;
            As[acol + 2][arow] = av.z;
            As[acol + 3][arow] = av.w;
        }
        // ---- load B tile -> Bs[k][n]
        if (!TRANSB) {
            const int n = n0 + bcol;
            float4 bv = make_float4(0.f, 0.f, 0.f, 0.f);
            if (n < N)  // N%4==0 guarantees full float4 when n < N
                bv = *reinterpret_cast<const float4*>(B + (long long)(k0 + brow) * ldb + n);
            Bs[brow][bcol + 0] = bv.x;
            Bs[brow][bcol + 1] = bv.y;
            Bs[brow][bcol + 2] = bv.z;
            Bs[brow][bcol + 3] = bv.w;
        } else {
            const int n = n0 + arow;
            float4 bv = make_float4(0.f, 0.f, 0.f, 0.f);
            if (n < N)
                bv = *reinterpret_cast<const float4*>(B + (long long)n * ldb + k0 + acol);
            Bs[acol + 0][arow] = bv.x;
            Bs[acol + 1][arow] = bv.y;
            Bs[acol + 2][arow] = bv.z;
            Bs[acol + 3][arow] = bv.w;
        }
        __syncthreads();

#pragma unroll
        for (int kk = 0; kk < 8; kk++) {
            float a[8], b[8];
#pragma unroll
            for (int i = 0; i < 8; i++) a[i] = As[kk][row_c + i];
#pragma unroll
            for (int j = 0; j < 8; j++) b[j] = Bs[kk][col_c + j];
#pragma unroll
            for (int i = 0; i < 8; i++)
#pragma unroll
                for (int j = 0; j < 8; j++) acc[i][j] += a[i] * b[j];
        }
        __syncthreads();
    }

#pragma unroll
    for (int i = 0; i < 8; i++) {
        const int m = m0 + row_c + i;
        if (m >= M) continue;
#pragma unroll
        for (int j = 0; j < 8; j++) {
            const int n = n0 + col_c + j;
            if (n < N) {
                float r = acc[i][j];
                if (bias) r += bias[n];
                C[(long long)m * ldc + n] = r;
            }
        }
    }
}

// ---------------------------------------------------------------------------
// Row softmax with pre-scale:  p <- softmax(p * scale), rowlen elements.
// ---------------------------------------------------------------------------
__global__ void softmax_rows(float* __restrict__ S, int rowlen, float scale)
{
    float* p = S + (long long)blockIdx.x * rowlen;
    const int tid = threadIdx.x;
    __shared__ float red[256];

    float mx = -1e30f;
    for (int i = tid; i < rowlen; i += 256) mx = fmaxf(mx, p[i]);
    red[tid] = mx;
    __syncthreads();
    for (int s = 128; s > 0; s >>= 1) {
        if (tid < s) red[tid] = fmaxf(red[tid], red[tid + s]);
        __syncthreads();
    }
    const float m = red[0] * scale;
    __syncthreads();

    float sum = 0.f;
    for (int i = tid; i < rowlen; i += 256) {
        float e = __expf(p[i] * scale - m);
        p[i] = e;
        sum += e;
    }
    red[tid] = sum;
    __syncthreads();
    for (int s = 128; s > 0; s >>= 1) {
        if (tid < s) red[tid] += red[tid + s];
        __syncthreads();
    }
    const float inv = 1.f / red[0];
    for (int i = tid; i < rowlen; i += 256) p[i] *= inv;
}

// ---------------------------------------------------------------------------
// Causal depthwise conv (D_CONV=4) + SiLU.
// x = xz[:, :4096] viewed as [b, t, 4096]; out xs[b, t, 4096].
// ---------------------------------------------------------------------------
__global__ void conv_silu_kernel(const float* __restrict__ xz,
                                 const float* __restrict__ w,
                                 const float* __restrict__ cb,
                                 float* __restrict__ xs)
{
    const long long idx = (long long)blockIdx.x * 256 + threadIdx.x; // < 8192*4096
    const int d = (int)(idx & 4095);
    const long long row = idx >> 12;
    const int t = (int)(row & 1023);
    const long long b = row >> 10;

    float accv = cb[d];
#pragma unroll
    for (int k = 0; k < 4; k++) {
        const int tt = t + k - 3;
        if (tt >= 0)
            accv += w[d * 4 + k] * xz[((b << 10) + tt) * 8192 + d];
    }
    xs[idx] = accv / (1.f + __expf(-accv));
}

// ---------------------------------------------------------------------------
// Softplus in-place (dt).
// ---------------------------------------------------------------------------
__global__ void softplus_kernel(float* __restrict__ p)
{
    const long long idx = (long long)blockIdx.x * 256 + threadIdx.x;
    const float v = p[idx];
    p[idx] = (v > 20.f) ? v : log1pf(__expf(v));
}

// ---------------------------------------------------------------------------
// Selective scan. One thread per (b, d); 16 states in registers.
// dbc row layout: [0:128)=dt_rank, [128:144)=B, [144:160)=C.
// ---------------------------------------------------------------------------
__global__ void scan_kernel(const float* __restrict__ xs,
                            const float* __restrict__ dt,
                            const float* __restrict__ dbc,
                            const float* __restrict__ A_log,
                            float* __restrict__ y)
{
    const int b = blockIdx.y;
    const int d = blockIdx.x * 256 + threadIdx.x;   // 0..4095

    float A[16], h[16];
#pragma unroll
    for (int n = 0; n < 16; n++) {
        A[n] = -__expf(A_log[d * 16 + n]);
        h[n] = 0.f;
    }

    const long long base = (long long)b * 1024;
    for (int t = 0; t < 1024; t++) {
        const long long row = base + t;
        const float xv  = xs[row * 4096 + d];
        const float dtv = dt[row * 4096 + d];
        const float* bc = dbc + row * 160;
        const float dtx = dtv * xv;
        float yv = 0.f;
#pragma unroll
        for (int n = 0; n < 16; n++) {
            const float dA = __expf(dtv * A[n]);
            h[n] = dA * h[n] + dtx * __ldg(bc + 128 + n);
            yv  += h[n] * __ldg(bc + 144 + n);
        }
        y[row * 4096 + d] = yv;
    }
}

// ---------------------------------------------------------------------------
// Gate: y2 = (y + D_skip[d]*xs) * silu(z),  z = xz[:, 4096+d].
// ---------------------------------------------------------------------------
__global__ void gate_kernel(const float* __restrict__ y,
                            const float* __restrict__ xs,
                            const float* __restrict__ xz,
                            const float* __restrict__ dskip,
                            float* __restrict__ y2)
{
    const long long idx = (long long)blockIdx.x * 256 + threadIdx.x;
    const int d = (int)(idx & 4095);
    const long long row = idx >> 12;
    const float z = xz[row * 8192 + 4096 + d];
    const float sz = z / (1.f + __expf(-z));
    y2[idx] = (y[idx] + dskip[d] * xs[idx]) * sz;
}

// ---------------------------------------------------------------------------
// Launch
// ---------------------------------------------------------------------------
extern "C" void kernel_launch(void* const* d_in, const int* in_sizes, int n_in,
                              void* d_out, int out_size)
{
    const float* X    = (const float*)d_in[0];   // imageFeature [8,1024,2048]
    const float* KF   = (const float*)d_in[1];   // kf
    const float* Wq   = (const float*)d_in[2];
    const float* bq   = (const float*)d_in[3];
    const float* Wk   = (const float*)d_in[4];
    const float* bk   = (const float*)d_in[5];
    const float* Wv   = (const float*)d_in[6];
    const float* bv   = (const float*)d_in[7];
    const float* Wo   = (const float*)d_in[8];
    const float* bo   = (const float*)d_in[9];
    const float* Win  = (const float*)d_in[10];  // [2048, 8192]
    const float* convw= (const float*)d_in[11];  // [4096, 4]
    const float* convb= (const float*)d_in[12];
    const float* Wex  = (const float*)d_in[13];  // [2048, 4096]
    const float* Wxp  = (const float*)d_in[14];  // [4096, 160]
    const float* Wdt  = (const float*)d_in[15];  // [128, 4096]
    const float* bdt  = (const float*)d_in[16];
    const float* Alog = (const float*)d_in[17];  // [4096, 16]
    const float* Dsk  = (const float*)d_in[18];
    const float* Wout = (const float*)d_in[19];  // [4096, 2048]
    float* out = (float*)d_out;                  // [2, 8, 1024, 2048]

    float* buf = nullptr;
    cudaGetSymbolAddress((void**)&buf, g_buf);
    float* q   = buf + OFF_Q;
    float* k   = buf + OFF_K;
    float* v   = buf + OFF_V;
    float* s   = buf + OFF_S;
    float* att = buf + OFF_ATT;
    float* xz  = buf + OFF_XZ;
    float* xs  = buf + OFF_XS;
    float* e   = buf + OFF_E;
    float* dbc = buf + OFF_DBC;
    float* dtb = buf + OFF_DT;
    float* y   = buf + OFF_Y;
    float* y2  = buf + OFF_Y2;

    const dim3 blk(256);

    // ===================== Attention branch =====================
    // q/k/v projections: [8192,2048] @ [2048,2048] + bias
    sgemm_kernel<false><<<dim3(16, 64, 1), blk>>>(X, Wq, bq, q,
        8192, 2048, 2048, 2048, 2048, 2048, 1, 0, 0, 0, 0, 0, 0);
    sgemm_kernel<false><<<dim3(16, 64, 1), blk>>>(X, Wk, bk, k,
        8192, 2048, 2048, 2048, 2048, 2048, 1, 0, 0, 0, 0, 0, 0);
    sgemm_kernel<false><<<dim3(16, 64, 1), blk>>>(X, Wv, bv, v,
        8192, 2048, 2048, 2048, 2048, 2048, 1, 0, 0, 0, 0, 0, 0);

    // scores[bh] = Q_bh @ K_bh^T   (64 batched [1024,256]x[256,1024])
    sgemm_kernel<true><<<dim3(8, 8, 64), blk>>>(q, k, nullptr, s,
        1024, 1024, 256, 2048, 2048, 1024,
        8, 2097152LL, 256LL, 2097152LL, 256LL, 8388608LL, 1048576LL);

    // softmax over k (with 1/sqrt(256) pre-scale)
    softmax_rows<<<65536, blk>>>(s, 1024, 0.0625f);

    // O_bh = S_bh @ V_bh   (64 batched [1024,1024]x[1024,256])
    sgemm_kernel<false><<<dim3(2, 8, 64), blk>>>(s, v, nullptr, att,
        1024, 256, 1024, 1024, 2048, 2048,
        8, 8388608LL, 1048576LL, 2097152LL, 256LL, 2097152LL, 256LL);

    // out[0] = att @ Wo + bo
    sgemm_kernel<false><<<dim3(16, 64, 1), blk>>>(att, Wo, bo, out,
        8192, 2048, 2048, 2048, 2048, 2048, 1, 0, 0, 0, 0, 0, 0);

    // ===================== Mamba branch =====================
    // xz = X @ W_in  [8192, 8192]
    sgemm_kernel<false><<<dim3(64, 64, 1), blk>>>(X, Win, nullptr, xz,
        8192, 8192, 2048, 2048, 8192, 8192, 1, 0, 0, 0, 0, 0, 0);

    // depthwise causal conv + silu -> xs
    conv_silu_kernel<<<131072, blk>>>(xz, convw, convb, xs);

    // e = kf @ W_extra  [8192, 4096]
    sgemm_kernel<false><<<dim3(32, 64, 1), blk>>>(KF, Wex, nullptr, e,
        8192, 4096, 2048, 2048, 4096, 4096, 1, 0, 0, 0, 0, 0, 0);

    // dbc = e @ W_xproj  [8192, 160]
    sgemm_kernel<false><<<dim3(2, 64, 1), blk>>>(e, Wxp, nullptr, dbc,
        8192, 160, 4096, 4096, 160, 160, 1, 0, 0, 0, 0, 0, 0);

    // dt_pre = dbc[:, :128] @ W_dt + b_dt  [8192, 4096]  (lda = 160)
    sgemm_kernel<false><<<dim3(32, 64, 1), blk>>>(dbc, Wdt, bdt, dtb,
        8192, 4096, 128, 160, 4096, 4096, 1, 0, 0, 0, 0, 0, 0);

    // softplus
    softplus_kernel<<<131072, blk>>>(dtb);

    // selective scan -> y
    scan_kernel<<<dim3(16, 8, 1), blk>>>(xs, dtb, dbc, Alog, y);

    // gate -> y2
    gate_kernel<<<131072, blk>>>(y, xs, xz, Dsk, y2);

    // out[1] = y2 @ W_out  [8192, 2048]
    sgemm_kernel<false><<<dim3(16, 64, 1), blk>>>(y2, Wout, nullptr, out + 16777216,
        8192, 2048, 4096, 4096, 2048, 2048, 1, 0, 0, 0, 0, 0, 0);
}